// round 15
// baseline (speedup 1.0000x reference)
#include <cuda_runtime.h>
#include <cuda_fp16.h>

#define BB 64
#define II 4096
#define CC 32
#define DD 16
#define KD 16

#define NCHUNK 32      // i-chunks for routing partials
#define RITERS 16      // i's per warp per routing CTA: NCHUNK*8*RITERS == II

#define NI1  32        // i's per uhat CTA
#define NCH1 (II/NI1)  // 128 s1-chunks

#define TILE_STRIDE 1056   // floats per buffered tile; chunk1 at +528 (==16 mod 32)
#define TCH1 528
#define OPH2 72            // Osm pitch (halves): 36 words == 4 mod 32

// Scratch (static device globals; no runtime allocation)
__device__ __half g_uhat[(size_t)BB * II * CC * DD];   // 268 MB, layout [b][i][n=c*16+D]
__device__ float  g_spart1[NCH1][BB * 512];            // 16.8 MB s1 partials [chunk][b][n]
__device__ float  g_spart3[8][BB * 512];               // 1 MB stage-1 partials
__device__ float  g_spart[NCHUNK][BB * CC * DD];       // routing partials [chunk][b][D][c]
__device__ float  g_V[BB * CC * DD];                   // Vsum, layout [b][n]

#define CP16(dst_u32, src_ptr) \
    asm volatile("cp.async.ca.shared.global [%0], [%1], 16;" \
                 :: "r"(dst_u32), "l"(src_ptr))

static __device__ __forceinline__ unsigned pack_h2(float a, float b) {
    __half2 h = __floats2half2_rn(a, b);
    return *reinterpret_cast<unsigned*>(&h);
}

// ---------- pass 0 (fp16 tensor cores, v9): cp.async double-buffered v7 ----------
// CTA = (chunk of NI1 i's, e): 128 threads = 4 warps; 64 b x 64 n (n-eighth e).
// warp wp = b-rowtile 16wp..16wp+15. m16n8k16 fp16 mma, fp32 acc.
// Tiles live in smem as f32 (cp.async direct); f32->f16 cvt at fragment load
// (same rounding as before -> identical u_hat). s1 fused; one flush per CTA.
__global__ __launch_bounds__(128) void uhat_kernel(
    const float* __restrict__ x, const float* __restrict__ w) {
    __shared__ __align__(16) float Wd[2][TILE_STRIDE];  // [buf][khalf-chunked 64n x 16d]
    __shared__ __align__(16) float xd[2][TILE_STRIDE];  // [buf][khalf-chunked 64b x 16d]
    __shared__ __half Osm[BB * OPH2];                    // [b*72 + n_local]

    const int tid   = threadIdx.x;
    const int chunk = blockIdx.x >> 3;
    const int e     = blockIdx.x & 7;    // n-eighth: global cols 64e .. 64e+63
    const int i0    = chunk * NI1;
    const int wp    = tid >> 5;
    const int l     = tid & 31;
    const int lr    = l >> 2, lc = l & 3;
    const int rsub  = l >> 3;            // store-phase row-sub 0..3
    const int colh  = (l & 7) * 8;       // store-phase col (halves)

    // cp.async slot assignment: copies c = tid, tid+128 for both W and x.
    // W: n = c>>2, piece = c&3 (4 x 16B per 16-float row, split across k-halves).
    // x: b = c>>2, piece = c&3.
    #define ISSUE_TILE(ii, buf)                                                  \
        {                                                                        \
            const float* wsrc = w + (size_t)(ii) * 8192 + e * 1024;              \
            const float* xsrc = x;                                               \
            _Pragma("unroll")                                                    \
            for (int q = 0; q < 2; q++) {                                        \
                int c_ = tid + q * 128;                                          \
                int n = c_ >> 2, piece = c_ & 3;                                 \
                int dw = ((piece & 2) ? TCH1 : 0) + n * 8 + (piece & 1) * 4;     \
                unsigned d_ = (unsigned)__cvta_generic_to_shared(&Wd[buf][dw]);  \
                CP16(d_, wsrc + n * 16 + piece * 4);                             \
            }                                                                    \
            _Pragma("unroll")                                                    \
            for (int q = 0; q < 2; q++) {                                        \
                int c_ = tid + q * 128;                                          \
                int b_ = c_ >> 2, piece = c_ & 3;                                \
                int dw = ((piece & 2) ? TCH1 : 0) + b_ * 8 + (piece & 1) * 4;    \
                unsigned d_ = (unsigned)__cvta_generic_to_shared(&xd[buf][dw]);  \
                CP16(d_, xsrc + ((size_t)b_ * II + (ii)) * KD + piece * 4);      \
            }                                                                    \
            asm volatile("cp.async.commit_group;");                              \
        }

    // prologue: group 0 -> buf 0
    ISSUE_TILE(i0, 0);

    float s1[8][4];
    #pragma unroll
    for (int nt = 0; nt < 8; nt++)
        { s1[nt][0] = 0.f; s1[nt][1] = 0.f; s1[nt][2] = 0.f; s1[nt][3] = 0.f; }

    for (int j = 0; j < NI1; j++) {
        const int i   = i0 + j;
        const int cur = j & 1;

        // issue next tile into the other buffer, then drain current group
        if (j + 1 < NI1) {
            ISSUE_TILE(i + 1, cur ^ 1);
            asm volatile("cp.async.wait_group 1;");
        } else {
            asm volatile("cp.async.wait_group 0;");
        }
        __syncthreads();   // current buffer visible to all threads

        // ---- fragments (f32 smem -> cvt -> f16) + mma: 8 n-tiles ----
        float cacc[8][4];
        #pragma unroll
        for (int nt = 0; nt < 8; nt++)
            { cacc[nt][0] = 0.f; cacc[nt][1] = 0.f; cacc[nt][2] = 0.f; cacc[nt][3] = 0.f; }
        {
            int r = 16 * wp + lr;
            float2 va0 = *(float2*)&xd[cur][r * 8 + 2 * lc];
            float2 va1 = *(float2*)&xd[cur][(r + 8) * 8 + 2 * lc];
            float2 va2 = *(float2*)&xd[cur][TCH1 + r * 8 + 2 * lc];
            float2 va3 = *(float2*)&xd[cur][TCH1 + (r + 8) * 8 + 2 * lc];
            unsigned a0 = pack_h2(va0.x, va0.y);
            unsigned a1 = pack_h2(va1.x, va1.y);
            unsigned a2 = pack_h2(va2.x, va2.y);
            unsigned a3 = pack_h2(va3.x, va3.y);
            #pragma unroll
            for (int nt = 0; nt < 8; nt++) {
                int nn = 8 * nt + lr;
                float2 vb0 = *(float2*)&Wd[cur][nn * 8 + 2 * lc];
                float2 vb1 = *(float2*)&Wd[cur][TCH1 + nn * 8 + 2 * lc];
                unsigned b0 = pack_h2(vb0.x, vb0.y);
                unsigned b1 = pack_h2(vb1.x, vb1.y);
                asm volatile(
                    "mma.sync.aligned.m16n8k16.row.col.f32.f16.f16.f32 "
                    "{%0,%1,%2,%3}, {%4,%5,%6,%7}, {%8,%9}, {%0,%1,%2,%3};"
                    : "+f"(cacc[nt][0]), "+f"(cacc[nt][1]),
                      "+f"(cacc[nt][2]), "+f"(cacc[nt][3])
                    : "r"(a0), "r"(a1), "r"(a2), "r"(a3), "r"(b0), "r"(b1));
            }
        }

        // ---- fused s1 accumulation (fragments live, free) ----
        #pragma unroll
        for (int nt = 0; nt < 8; nt++) {
            s1[nt][0] += cacc[nt][0]; s1[nt][1] += cacc[nt][1];
            s1[nt][2] += cacc[nt][2]; s1[nt][3] += cacc[nt][3];
        }

        // ---- epilogue: fragments -> Osm rows 16wp..16wp+15 (own-warp rows) ----
        {
            int r0 = 16 * wp + lr, r1 = r0 + 8;
            #pragma unroll
            for (int nt = 0; nt < 8; nt++) {
                int col = 8 * nt + 2 * lc;
                *(__half2*)&Osm[r0 * OPH2 + col] = __floats2half2_rn(cacc[nt][0], cacc[nt][1]);
                *(__half2*)&Osm[r1 * OPH2 + col] = __floats2half2_rn(cacc[nt][2], cacc[nt][3]);
            }
        }
        __syncwarp();

        // ---- store: 4 iters; per iter warp stores 4 rows x 128B contiguous ----
        #pragma unroll
        for (int r = 0; r < 4; r++) {
            int b = 16 * wp + 4 * r + rsub;
            uint4 v = *(uint4*)&Osm[b * OPH2 + colh];
            *(uint4*)(g_uhat + ((size_t)b * II + i) * (CC * DD) + 64 * e + colh) = v;
        }
        __syncthreads();   // all reads of buf cur done before it is re-filled (j+2)
    }

    // ---- flush s1 partials (scale 1/32), full 32B sectors ----
    {
        float* dst = g_spart1[chunk];
        #pragma unroll
        for (int nt = 0; nt < 8; nt++) {
            int col = 64 * e + 8 * nt + 2 * lc;
            #pragma unroll
            for (int rp = 0; rp < 2; rp++) {
                int rowg = 16 * wp + lr + 8 * rp;
                float2 v2 = make_float2(s1[nt][rp * 2] * (1.0f / 32.0f),
                                        s1[nt][rp * 2 + 1] * (1.0f / 32.0f));
                *(float2*)&dst[rowg * 512 + col] = v2;
            }
        }
    }
    #undef ISSUE_TILE
}

// ---------- s1 reduce stage 1: 128 chunks -> 8 partials ----------
__global__ void reduce_stage1() {
    int gid = blockIdx.x * blockDim.x + threadIdx.x;   // 0..262143
    int g = gid >> 15, t = gid & 32767;
    float s = 0.0f;
    #pragma unroll
    for (int ch = 0; ch < NCH1 / 8; ch++)
        s += g_spart1[g * (NCH1 / 8) + ch][t];
    g_spart3[g][t] = s;
}

// ---------- s1 reduce stage 2 + squash -> g_V = v1 ----------
__global__ void reduce_stage2() {
    int t = blockIdx.x * blockDim.x + threadIdx.x;     // [b][n], n fastest
    float s = 0.0f;
    #pragma unroll
    for (int g = 0; g < 8; g++) s += g_spart3[g][t];

    float sq = s * s;
    #pragma unroll
    for (int off = 1; off < 16; off <<= 1)
        sq += __shfl_xor_sync(0xffffffffu, sq, off);   // capsule's 16 D's

    float f = 1.0f / ((1.0f + sq) * sqrtf(sq + 1e-9f));
    g_V[t] = s * f;
}

// ---------- routing pass (full softmax vs V) ----------
// __launch_bounds__(256, 3): keep regs <= 80 so 3 CTAs stay resident (R14 win).
__global__ __launch_bounds__(256, 3) void routing_kernel() {
    const int b     = blockIdx.y;
    const int chunk = blockIdx.x;
    const int warp  = threadIdx.x >> 5;
    const int c     = threadIdx.x & 31;

    float V[DD];
    #pragma unroll
    for (int D = 0; D < DD; D++) V[D] = g_V[(b * CC + c) * DD + D];

    float sacc[DD];
    #pragma unroll
    for (int D = 0; D < DD; D++) sacc[D] = 0.0f;

    const int i0 = chunk * (8 * RITERS) + warp * RITERS;
    const uint4* p = (const uint4*)(g_uhat + ((size_t)b * II + i0) * (CC * DD)) + c * 2;

    uint4 q0 = p[0];
    uint4 q1 = p[1];

    #pragma unroll 4
    for (int k = 0; k < RITERS; k++) {
        uint4 n0 = q0, n1 = q1;
        if (k + 1 < RITERS) {
            n0 = p[(k + 1) * 64];
            n1 = p[(k + 1) * 64 + 1];
        }

        float u[DD];
        unsigned rr[8] = {q0.x, q0.y, q0.z, q0.w, q1.x, q1.y, q1.z, q1.w};
        #pragma unroll
        for (int pp = 0; pp < 8; pp++) {
            __half2 h = *reinterpret_cast<__half2*>(&rr[pp]);
            float2 f = __half22float2(h);
            u[2 * pp]     = f.x;
            u[2 * pp + 1] = f.y;
        }

        float logit = 0.0f;
        #pragma unroll
        for (int D = 0; D < DD; D++) logit = fmaf(u[D], V[D], logit);
        float m = logit;
        #pragma unroll
        for (int off = 16; off > 0; off >>= 1)
            m = fmaxf(m, __shfl_xor_sync(0xffffffffu, m, off));
        float ev = __expf(logit - m);
        float ssum = ev;
        #pragma unroll
        for (int off = 16; off > 0; off >>= 1)
            ssum += __shfl_xor_sync(0xffffffffu, ssum, off);
        float cij = ev / ssum;

        #pragma unroll
        for (int D = 0; D < DD; D++) sacc[D] = fmaf(cij, u[D], sacc[D]);

        q0 = n0; q1 = n1;
    }

    __shared__ float red[8][CC * DD];
    #pragma unroll
    for (int D = 0; D < DD; D++) red[warp][D * 32 + c] = sacc[D];
    __syncthreads();

    for (int t = threadIdx.x; t < CC * DD; t += 256) {
        float v = 0.0f;
        #pragma unroll
        for (int wq = 0; wq < 8; wq++) v += red[wq][t];
        g_spart[chunk][b * (CC * DD) + t] = v;   // [chunk][b][D][c]
    }
}

// ---------- squash (routing partials): pass 1 -> g_V += v2; pass 2 -> out = v3 ----
__global__ void squash_kernel(float* __restrict__ out, int pass) {
    int t = blockIdx.x * blockDim.x + threadIdx.x;   // (b,c,D), D fastest
    int bc = t >> 4, D = t & 15;
    int b = bc >> 5, c = bc & 31;
    int addr = b * (CC * DD) + D * 32 + c;           // [b][D][c] partial layout

    float s = 0.0f;
    #pragma unroll
    for (int ch = 0; ch < NCHUNK; ch++) s += g_spart[ch][addr];

    float sq = s * s;
    #pragma unroll
    for (int off = 1; off < 16; off <<= 1)
        sq += __shfl_xor_sync(0xffffffffu, sq, off);

    float f = 1.0f / ((1.0f + sq) * sqrtf(sq + 1e-9f));
    float v = s * f;

    if (pass == 1) g_V[t] += v;
    else           out[t] = v;
}

extern "C" void kernel_launch(void* const* d_in, const int* in_sizes, int n_in,
                              void* d_out, int out_size) {
    const float* x = (const float*)d_in[0];
    const float* w = (const float*)d_in[1];
    float* out = (float*)d_out;

    uhat_kernel<<<NCH1 * 8, 128>>>(x, w);       // u_hat + fused s1 partials
    reduce_stage1<<<1024, 256>>>();
    reduce_stage2<<<128, 256>>>();              // g_V = v1

    routing_kernel<<<dim3(NCHUNK, BB), 256>>>();  // pass 2
    squash_kernel<<<128, 256>>>(out, 1);          // g_V += v2

    routing_kernel<<<dim3(NCHUNK, BB), 256>>>();  // pass 3
    squash_kernel<<<128, 256>>>(out, 2);          // out = v3
}

// round 16
// speedup vs baseline: 1.0562x; 1.0562x over previous
#include <cuda_runtime.h>
#include <cuda_fp16.h>

#define BB 64
#define II 4096
#define CC 32
#define DD 16
#define KD 16

#define NCHUNK 32      // i-chunks for routing partials
#define RITERS 16      // i's per warp per routing CTA: NCHUNK*8*RITERS == II

#define NI1  32        // i's per uhat CTA
#define NCH1 (II/NI1)  // 128 s1-chunks

#define WQ1H 544       // Wf chunk1 base (halves): word 272 == 16 mod 32
#define XQ1H 544       // xf chunk1 base (halves)
#define OPH2 72        // Osm pitch (halves): 36 words == 4 mod 32

// Scratch (static device globals; no runtime allocation)
__device__ __half g_uhat[(size_t)BB * II * CC * DD];   // 268 MB, layout [b][i][n=c*16+D]
__device__ float  g_spart1[NCH1][BB * 512];            // 16.8 MB s1 partials [chunk][b][n]
__device__ float  g_spart3[8][BB * 512];               // 1 MB stage-1 partials
__device__ float  g_spart[NCHUNK][BB * CC * DD];       // routing partials [chunk][b][D][c]
__device__ float  g_V[BB * CC * DD];                   // Vsum, layout [b][n]

// ---------- pass 0 (fp16 tensor cores, v7 + streaming stores) ----------
// CTA = (chunk of NI1 i's, e): 128 threads = 4 warps; 64 b x 64 n (n-eighth e).
// warp wp = b-rowtile 16wp..16wp+15. m16n8k16 fp16 mma, fp32 acc.
// u_hat stores use __stcs (evict-first): u_hat can never fit L2; default
// write-allocate evicts the x stream that relies on 8x L2 reuse.
__global__ __launch_bounds__(128) void uhat_kernel(
    const float* __restrict__ x, const float* __restrict__ w) {
    __shared__ __half Wf[WQ1H + 512];   // 64n x 16d fp16, chunked by k-half
    __shared__ __half xf[XQ1H + 512];   // 64b x 16d fp16, chunked by k-half
    __shared__ __half Osm[BB * OPH2];   // [b*72 + n_local]

    const int tid   = threadIdx.x;
    const int chunk = blockIdx.x >> 3;
    const int e     = blockIdx.x & 7;    // n-eighth: global cols 64e .. 64e+63
    const int wp    = tid >> 5;
    const int l     = tid & 31;
    const int lr    = l >> 2, lc = l & 3;
    const int rsub  = l >> 3;            // store-phase row-sub 0..3
    const int colh  = (l & 7) * 8;       // store-phase col (halves)

    float s1[8][4];
    #pragma unroll
    for (int nt = 0; nt < 8; nt++)
        { s1[nt][0] = 0.f; s1[nt][1] = 0.f; s1[nt][2] = 0.f; s1[nt][3] = 0.f; }

    for (int j = 0; j < NI1; j++) {
        const int i = chunk * NI1 + j;

        // ---- fill: W slab (64n x 16d) and x tile (64b x 16d), f32 -> f16 ----
        {
            const float4* w4 = (const float4*)(w + (size_t)i * 8192 + e * 1024);
            #pragma unroll
            for (int q = 0; q < 2; q++) {
                int slot = tid + q * 128;
                int n = slot >> 2, d0 = (slot & 3) * 4;
                float4 v = w4[slot];
                int base = (d0 >= 8 ? WQ1H : 0) + n * 8 + (d0 & 7);
                *(__half2*)&Wf[base]     = __floats2half2_rn(v.x, v.y);
                *(__half2*)&Wf[base + 2] = __floats2half2_rn(v.z, v.w);
            }
            #pragma unroll
            for (int q = 0; q < 2; q++) {
                int slot = tid + q * 128;
                int b = slot >> 2, d0 = (slot & 3) * 4;
                float4 v = *(const float4*)(x + ((size_t)b * II + i) * KD + d0);
                int base = (d0 >= 8 ? XQ1H : 0) + b * 8 + (d0 & 7);
                *(__half2*)&xf[base]     = __floats2half2_rn(v.x, v.y);
                *(__half2*)&xf[base + 2] = __floats2half2_rn(v.z, v.w);
            }
        }
        __syncthreads();

        // ---- fragments + mma: 8 n-tiles ----
        float cacc[8][4];
        #pragma unroll
        for (int nt = 0; nt < 8; nt++)
            { cacc[nt][0] = 0.f; cacc[nt][1] = 0.f; cacc[nt][2] = 0.f; cacc[nt][3] = 0.f; }
        {
            int r = 16 * wp + lr;
            unsigned a0 = *(unsigned*)&xf[r * 8 + 2 * lc];
            unsigned a1 = *(unsigned*)&xf[(r + 8) * 8 + 2 * lc];
            unsigned a2 = *(unsigned*)&xf[XQ1H + r * 8 + 2 * lc];
            unsigned a3 = *(unsigned*)&xf[XQ1H + (r + 8) * 8 + 2 * lc];
            #pragma unroll
            for (int nt = 0; nt < 8; nt++) {
                int nn = 8 * nt + lr;
                unsigned b0 = *(unsigned*)&Wf[nn * 8 + 2 * lc];
                unsigned b1 = *(unsigned*)&Wf[WQ1H + nn * 8 + 2 * lc];
                asm volatile(
                    "mma.sync.aligned.m16n8k16.row.col.f32.f16.f16.f32 "
                    "{%0,%1,%2,%3}, {%4,%5,%6,%7}, {%8,%9}, {%0,%1,%2,%3};"
                    : "+f"(cacc[nt][0]), "+f"(cacc[nt][1]),
                      "+f"(cacc[nt][2]), "+f"(cacc[nt][3])
                    : "r"(a0), "r"(a1), "r"(a2), "r"(a3), "r"(b0), "r"(b1));
            }
        }

        // ---- fused s1 accumulation (fragments live, free) ----
        #pragma unroll
        for (int nt = 0; nt < 8; nt++) {
            s1[nt][0] += cacc[nt][0]; s1[nt][1] += cacc[nt][1];
            s1[nt][2] += cacc[nt][2]; s1[nt][3] += cacc[nt][3];
        }

        // ---- epilogue: fragments -> Osm rows 16wp..16wp+15 (own-warp rows only) ----
        {
            int r0 = 16 * wp + lr, r1 = r0 + 8;
            #pragma unroll
            for (int nt = 0; nt < 8; nt++) {
                int col = 8 * nt + 2 * lc;
                *(__half2*)&Osm[r0 * OPH2 + col] = __floats2half2_rn(cacc[nt][0], cacc[nt][1]);
                *(__half2*)&Osm[r1 * OPH2 + col] = __floats2half2_rn(cacc[nt][2], cacc[nt][3]);
            }
        }
        __syncwarp();

        // ---- store: 4 iters; warp stores 4 rows x 128B contiguous (evict-first) ----
        #pragma unroll
        for (int r = 0; r < 4; r++) {
            int b = 16 * wp + 4 * r + rsub;
            uint4 v = *(uint4*)&Osm[b * OPH2 + colh];
            __stcs((uint4*)(g_uhat + ((size_t)b * II + i) * (CC * DD) + 64 * e + colh), v);
        }
        __syncthreads();   // mma/Osm reads done before next fill/epilogue
    }

    // ---- flush s1 partials (scale 1/32), streaming stores ----
    {
        float* dst = g_spart1[chunk];
        #pragma unroll
        for (int nt = 0; nt < 8; nt++) {
            int col = 64 * e + 8 * nt + 2 * lc;
            #pragma unroll
            for (int rp = 0; rp < 2; rp++) {
                int rowg = 16 * wp + lr + 8 * rp;
                float2 v2 = make_float2(s1[nt][rp * 2] * (1.0f / 32.0f),
                                        s1[nt][rp * 2 + 1] * (1.0f / 32.0f));
                __stcs((float2*)&dst[rowg * 512 + col], v2);
            }
        }
    }
}

// ---------- s1 reduce stage 1: 128 chunks -> 8 partials ----------
__global__ void reduce_stage1() {
    int gid = blockIdx.x * blockDim.x + threadIdx.x;   // 0..262143
    int g = gid >> 15, t = gid & 32767;
    float s = 0.0f;
    #pragma unroll
    for (int ch = 0; ch < NCH1 / 8; ch++)
        s += __ldcs(&g_spart1[g * (NCH1 / 8) + ch][t]);
    g_spart3[g][t] = s;
}

// ---------- s1 reduce stage 2 + squash -> g_V = v1 ----------
__global__ void reduce_stage2() {
    int t = blockIdx.x * blockDim.x + threadIdx.x;     // [b][n], n fastest
    float s = 0.0f;
    #pragma unroll
    for (int g = 0; g < 8; g++) s += g_spart3[g][t];

    float sq = s * s;
    #pragma unroll
    for (int off = 1; off < 16; off <<= 1)
        sq += __shfl_xor_sync(0xffffffffu, sq, off);   // capsule's 16 D's

    float f = 1.0f / ((1.0f + sq) * sqrtf(sq + 1e-9f));
    g_V[t] = s * f;
}

// ---------- routing pass (full softmax vs V); streaming u_hat loads ----------
// __launch_bounds__(256, 3): keep regs <= 80 so 3 CTAs stay resident (R14 win).
__global__ __launch_bounds__(256, 3) void routing_kernel() {
    const int b     = blockIdx.y;
    const int chunk = blockIdx.x;
    const int warp  = threadIdx.x >> 5;
    const int c     = threadIdx.x & 31;

    float V[DD];
    #pragma unroll
    for (int D = 0; D < DD; D++) V[D] = g_V[(b * CC + c) * DD + D];

    float sacc[DD];
    #pragma unroll
    for (int D = 0; D < DD; D++) sacc[D] = 0.0f;

    const int i0 = chunk * (8 * RITERS) + warp * RITERS;
    const uint4* p = (const uint4*)(g_uhat + ((size_t)b * II + i0) * (CC * DD)) + c * 2;

    uint4 q0 = __ldcs(p);
    uint4 q1 = __ldcs(p + 1);

    #pragma unroll 4
    for (int k = 0; k < RITERS; k++) {
        uint4 n0 = q0, n1 = q1;
        if (k + 1 < RITERS) {
            n0 = __ldcs(p + (k + 1) * 64);
            n1 = __ldcs(p + (k + 1) * 64 + 1);
        }

        float u[DD];
        unsigned rr[8] = {q0.x, q0.y, q0.z, q0.w, q1.x, q1.y, q1.z, q1.w};
        #pragma unroll
        for (int pp = 0; pp < 8; pp++) {
            __half2 h = *reinterpret_cast<__half2*>(&rr[pp]);
            float2 f = __half22float2(h);
            u[2 * pp]     = f.x;
            u[2 * pp + 1] = f.y;
        }

        float logit = 0.0f;
        #pragma unroll
        for (int D = 0; D < DD; D++) logit = fmaf(u[D], V[D], logit);
        float m = logit;
        #pragma unroll
        for (int off = 16; off > 0; off >>= 1)
            m = fmaxf(m, __shfl_xor_sync(0xffffffffu, m, off));
        float ev = __expf(logit - m);
        float ssum = ev;
        #pragma unroll
        for (int off = 16; off > 0; off >>= 1)
            ssum += __shfl_xor_sync(0xffffffffu, ssum, off);
        float cij = ev / ssum;

        #pragma unroll
        for (int D = 0; D < DD; D++) sacc[D] = fmaf(cij, u[D], sacc[D]);

        q0 = n0; q1 = n1;
    }

    __shared__ float red[8][CC * DD];
    #pragma unroll
    for (int D = 0; D < DD; D++) red[warp][D * 32 + c] = sacc[D];
    __syncthreads();

    for (int t = threadIdx.x; t < CC * DD; t += 256) {
        float v = 0.0f;
        #pragma unroll
        for (int wq = 0; wq < 8; wq++) v += red[wq][t];
        g_spart[chunk][b * (CC * DD) + t] = v;   // [chunk][b][D][c]
    }
}

// ---------- squash (routing partials): pass 1 -> g_V += v2; pass 2 -> out = v3 ----
__global__ void squash_kernel(float* __restrict__ out, int pass) {
    int t = blockIdx.x * blockDim.x + threadIdx.x;   // (b,c,D), D fastest
    int bc = t >> 4, D = t & 15;
    int b = bc >> 5, c = bc & 31;
    int addr = b * (CC * DD) + D * 32 + c;           // [b][D][c] partial layout

    float s = 0.0f;
    #pragma unroll
    for (int ch = 0; ch < NCHUNK; ch++) s += g_spart[ch][addr];

    float sq = s * s;
    #pragma unroll
    for (int off = 1; off < 16; off <<= 1)
        sq += __shfl_xor_sync(0xffffffffu, sq, off);

    float f = 1.0f / ((1.0f + sq) * sqrtf(sq + 1e-9f));
    float v = s * f;

    if (pass == 1) g_V[t] += v;
    else           out[t] = v;
}

extern "C" void kernel_launch(void* const* d_in, const int* in_sizes, int n_in,
                              void* d_out, int out_size) {
    const float* x = (const float*)d_in[0];
    const float* w = (const float*)d_in[1];
    float* out = (float*)d_out;

    uhat_kernel<<<NCH1 * 8, 128>>>(x, w);       // u_hat + fused s1 partials
    reduce_stage1<<<1024, 256>>>();
    reduce_stage2<<<128, 256>>>();              // g_V = v1

    routing_kernel<<<dim3(NCHUNK, BB), 256>>>();  // pass 2
    squash_kernel<<<128, 256>>>(out, 1);          // g_V += v2

    routing_kernel<<<dim3(NCHUNK, BB), 256>>>();  // pass 3
    squash_kernel<<<128, 256>>>(out, 2);          // out = v3
}

// round 17
// speedup vs baseline: 1.1070x; 1.0481x over previous
#include <cuda_runtime.h>
#include <cuda_fp16.h>

#define BB 64
#define II 4096
#define CC 32
#define DD 16
#define KD 16

#define NCHUNK 32      // i-chunks for routing partials
#define RITERS 16      // i's per warp per routing CTA: NCHUNK*8*RITERS == II

#define NI1  32        // i's per uhat CTA
#define NCH1 (II/NI1)  // 128 s1-chunks

#define WQ1H 544       // Wf chunk1 base (halves): word 272 == 16 mod 32
#define XQ1H 544       // xf chunk1 base (halves)
#define OPH2 72        // Osm pitch (halves): 36 words == 4 mod 32

// Scratch (static device globals; no runtime allocation)
__device__ __half g_uhat[(size_t)BB * II * CC * DD];   // 268 MB, layout [b][i][n=c*16+D]
__device__ float  g_spart1[NCH1][BB * 512];            // 16.8 MB s1 partials [chunk][b][n]
__device__ float  g_spart3[8][BB * 512];               // 1 MB stage-1 partials
__device__ float  g_spart[NCHUNK][BB * CC * DD];       // routing partials [chunk][b][D][c]
__device__ float  g_V[BB * CC * DD];                   // Vsum, layout [b][n]

// ---------- pass 0 (fp16 tensor cores, v7 + streaming stores) ----------
// CTA = (chunk of NI1 i's, e): 128 threads = 4 warps; 64 b x 64 n (n-eighth e).
// warp wp = b-rowtile 16wp..16wp+15. m16n8k16 fp16 mma, fp32 acc.
__global__ __launch_bounds__(128) void uhat_kernel(
    const float* __restrict__ x, const float* __restrict__ w) {
    __shared__ __half Wf[WQ1H + 512];   // 64n x 16d fp16, chunked by k-half
    __shared__ __half xf[XQ1H + 512];   // 64b x 16d fp16, chunked by k-half
    __shared__ __half Osm[BB * OPH2];   // [b*72 + n_local]

    const int tid   = threadIdx.x;
    const int chunk = blockIdx.x >> 3;
    const int e     = blockIdx.x & 7;    // n-eighth: global cols 64e .. 64e+63
    const int wp    = tid >> 5;
    const int l     = tid & 31;
    const int lr    = l >> 2, lc = l & 3;
    const int rsub  = l >> 3;            // store-phase row-sub 0..3
    const int colh  = (l & 7) * 8;       // store-phase col (halves)

    float s1[8][4];
    #pragma unroll
    for (int nt = 0; nt < 8; nt++)
        { s1[nt][0] = 0.f; s1[nt][1] = 0.f; s1[nt][2] = 0.f; s1[nt][3] = 0.f; }

    for (int j = 0; j < NI1; j++) {
        const int i = chunk * NI1 + j;

        // ---- fill: W slab (64n x 16d) and x tile (64b x 16d), f32 -> f16 ----
        {
            const float4* w4 = (const float4*)(w + (size_t)i * 8192 + e * 1024);
            #pragma unroll
            for (int q = 0; q < 2; q++) {
                int slot = tid + q * 128;
                int n = slot >> 2, d0 = (slot & 3) * 4;
                float4 v = w4[slot];
                int base = (d0 >= 8 ? WQ1H : 0) + n * 8 + (d0 & 7);
                *(__half2*)&Wf[base]     = __floats2half2_rn(v.x, v.y);
                *(__half2*)&Wf[base + 2] = __floats2half2_rn(v.z, v.w);
            }
            #pragma unroll
            for (int q = 0; q < 2; q++) {
                int slot = tid + q * 128;
                int b = slot >> 2, d0 = (slot & 3) * 4;
                float4 v = *(const float4*)(x + ((size_t)b * II + i) * KD + d0);
                int base = (d0 >= 8 ? XQ1H : 0) + b * 8 + (d0 & 7);
                *(__half2*)&xf[base]     = __floats2half2_rn(v.x, v.y);
                *(__half2*)&xf[base + 2] = __floats2half2_rn(v.z, v.w);
            }
        }
        __syncthreads();

        // ---- fragments + mma: 8 n-tiles ----
        float cacc[8][4];
        #pragma unroll
        for (int nt = 0; nt < 8; nt++)
            { cacc[nt][0] = 0.f; cacc[nt][1] = 0.f; cacc[nt][2] = 0.f; cacc[nt][3] = 0.f; }
        {
            int r = 16 * wp + lr;
            unsigned a0 = *(unsigned*)&xf[r * 8 + 2 * lc];
            unsigned a1 = *(unsigned*)&xf[(r + 8) * 8 + 2 * lc];
            unsigned a2 = *(unsigned*)&xf[XQ1H + r * 8 + 2 * lc];
            unsigned a3 = *(unsigned*)&xf[XQ1H + (r + 8) * 8 + 2 * lc];
            #pragma unroll
            for (int nt = 0; nt < 8; nt++) {
                int nn = 8 * nt + lr;
                unsigned b0 = *(unsigned*)&Wf[nn * 8 + 2 * lc];
                unsigned b1 = *(unsigned*)&Wf[WQ1H + nn * 8 + 2 * lc];
                asm volatile(
                    "mma.sync.aligned.m16n8k16.row.col.f32.f16.f16.f32 "
                    "{%0,%1,%2,%3}, {%4,%5,%6,%7}, {%8,%9}, {%0,%1,%2,%3};"
                    : "+f"(cacc[nt][0]), "+f"(cacc[nt][1]),
                      "+f"(cacc[nt][2]), "+f"(cacc[nt][3])
                    : "r"(a0), "r"(a1), "r"(a2), "r"(a3), "r"(b0), "r"(b1));
            }
        }

        // ---- fused s1 accumulation (fragments live, free) ----
        #pragma unroll
        for (int nt = 0; nt < 8; nt++) {
            s1[nt][0] += cacc[nt][0]; s1[nt][1] += cacc[nt][1];
            s1[nt][2] += cacc[nt][2]; s1[nt][3] += cacc[nt][3];
        }

        // ---- epilogue: fragments -> Osm rows 16wp..16wp+15 (own-warp rows only) ----
        {
            int r0 = 16 * wp + lr, r1 = r0 + 8;
            #pragma unroll
            for (int nt = 0; nt < 8; nt++) {
                int col = 8 * nt + 2 * lc;
                *(__half2*)&Osm[r0 * OPH2 + col] = __floats2half2_rn(cacc[nt][0], cacc[nt][1]);
                *(__half2*)&Osm[r1 * OPH2 + col] = __floats2half2_rn(cacc[nt][2], cacc[nt][3]);
            }
        }
        __syncwarp();

        // ---- store: 4 iters; warp stores 4 rows x 128B contiguous (evict-first) ----
        #pragma unroll
        for (int r = 0; r < 4; r++) {
            int b = 16 * wp + 4 * r + rsub;
            uint4 v = *(uint4*)&Osm[b * OPH2 + colh];
            __stcs((uint4*)(g_uhat + ((size_t)b * II + i) * (CC * DD) + 64 * e + colh), v);
        }
        __syncthreads();   // mma/Osm reads done before next fill/epilogue
    }

    // ---- flush s1 partials (scale 1/32), streaming stores ----
    {
        float* dst = g_spart1[chunk];
        #pragma unroll
        for (int nt = 0; nt < 8; nt++) {
            int col = 64 * e + 8 * nt + 2 * lc;
            #pragma unroll
            for (int rp = 0; rp < 2; rp++) {
                int rowg = 16 * wp + lr + 8 * rp;
                float2 v2 = make_float2(s1[nt][rp * 2] * (1.0f / 32.0f),
                                        s1[nt][rp * 2 + 1] * (1.0f / 32.0f));
                __stcs((float2*)&dst[rowg * 512 + col], v2);
            }
        }
    }
}

// ---------- s1 reduce stage 1: 128 chunks -> 8 partials ----------
__global__ void reduce_stage1() {
    int gid = blockIdx.x * blockDim.x + threadIdx.x;   // 0..262143
    int g = gid >> 15, t = gid & 32767;
    float s = 0.0f;
    #pragma unroll
    for (int ch = 0; ch < NCH1 / 8; ch++)
        s += __ldcs(&g_spart1[g * (NCH1 / 8) + ch][t]);
    g_spart3[g][t] = s;
}

// ---------- s1 reduce stage 2 + squash -> g_V = v1 ----------
__global__ void reduce_stage2() {
    int t = blockIdx.x * blockDim.x + threadIdx.x;     // [b][n], n fastest
    float s = 0.0f;
    #pragma unroll
    for (int g = 0; g < 8; g++) s += g_spart3[g][t];

    float sq = s * s;
    #pragma unroll
    for (int off = 1; off < 16; off <<= 1)
        sq += __shfl_xor_sync(0xffffffffu, sq, off);   // capsule's 16 D's

    float f = 1.0f / ((1.0f + sq) * sqrtf(sq + 1e-9f));
    g_V[t] = s * f;
}

// ---------- routing pass (full softmax vs V); triple-buffered streaming loads ----
// __launch_bounds__(256, 2): trade occupancy (24 -> 16 warps) for MLP depth 3.
// Little's law: 16 warps x ~1.5-3KB in flight > 23KB/SM needed to saturate DRAM;
// R12 showed the 2-CTA config was latency-starved at MLP 2 — depth 3 fixes that.
__global__ __launch_bounds__(256, 2) void routing_kernel() {
    const int b     = blockIdx.y;
    const int chunk = blockIdx.x;
    const int warp  = threadIdx.x >> 5;
    const int c     = threadIdx.x & 31;

    float V[DD];
    #pragma unroll
    for (int D = 0; D < DD; D++) V[D] = g_V[(b * CC + c) * DD + D];

    float sacc[DD];
    #pragma unroll
    for (int D = 0; D < DD; D++) sacc[D] = 0.0f;

    const int i0 = chunk * (8 * RITERS) + warp * RITERS;
    const uint4* p = (const uint4*)(g_uhat + ((size_t)b * II + i0) * (CC * DD)) + c * 2;

    // triple buffer: q = iter k (ready), r = k+1 (in flight), m = k+2 (issued in loop)
    uint4 q0 = __ldcs(p);
    uint4 q1 = __ldcs(p + 1);
    uint4 r0 = __ldcs(p + 64);
    uint4 r1 = __ldcs(p + 65);

    #pragma unroll 4
    for (int k = 0; k < RITERS; k++) {
        uint4 m0, m1;
        if (k + 2 < RITERS) {
            m0 = __ldcs(p + (k + 2) * 64);
            m1 = __ldcs(p + (k + 2) * 64 + 1);
        }

        float u[DD];
        unsigned rr[8] = {q0.x, q0.y, q0.z, q0.w, q1.x, q1.y, q1.z, q1.w};
        #pragma unroll
        for (int pp = 0; pp < 8; pp++) {
            __half2 h = *reinterpret_cast<__half2*>(&rr[pp]);
            float2 f = __half22float2(h);
            u[2 * pp]     = f.x;
            u[2 * pp + 1] = f.y;
        }

        float logit = 0.0f;
        #pragma unroll
        for (int D = 0; D < DD; D++) logit = fmaf(u[D], V[D], logit);
        float m = logit;
        #pragma unroll
        for (int off = 16; off > 0; off >>= 1)
            m = fmaxf(m, __shfl_xor_sync(0xffffffffu, m, off));
        float ev = __expf(logit - m);
        float ssum = ev;
        #pragma unroll
        for (int off = 16; off > 0; off >>= 1)
            ssum += __shfl_xor_sync(0xffffffffu, ssum, off);
        float cij = ev / ssum;

        #pragma unroll
        for (int D = 0; D < DD; D++) sacc[D] = fmaf(cij, u[D], sacc[D]);

        q0 = r0; q1 = r1;
        if (k + 2 < RITERS) { r0 = m0; r1 = m1; }
    }

    __shared__ float red[8][CC * DD];
    #pragma unroll
    for (int D = 0; D < DD; D++) red[warp][D * 32 + c] = sacc[D];
    __syncthreads();

    for (int t = threadIdx.x; t < CC * DD; t += 256) {
        float v = 0.0f;
        #pragma unroll
        for (int wq = 0; wq < 8; wq++) v += red[wq][t];
        g_spart[chunk][b * (CC * DD) + t] = v;   // [chunk][b][D][c]
    }
}

// ---------- squash (routing partials): pass 1 -> g_V += v2; pass 2 -> out = v3 ----
__global__ void squash_kernel(float* __restrict__ out, int pass) {
    int t = blockIdx.x * blockDim.x + threadIdx.x;   // (b,c,D), D fastest
    int bc = t >> 4, D = t & 15;
    int b = bc >> 5, c = bc & 31;
    int addr = b * (CC * DD) + D * 32 + c;           // [b][D][c] partial layout

    float s = 0.0f;
    #pragma unroll
    for (int ch = 0; ch < NCHUNK; ch++) s += g_spart[ch][addr];

    float sq = s * s;
    #pragma unroll
    for (int off = 1; off < 16; off <<= 1)
        sq += __shfl_xor_sync(0xffffffffu, sq, off);

    float f = 1.0f / ((1.0f + sq) * sqrtf(sq + 1e-9f));
    float v = s * f;

    if (pass == 1) g_V[t] += v;
    else           out[t] = v;
}

extern "C" void kernel_launch(void* const* d_in, const int* in_sizes, int n_in,
                              void* d_out, int out_size) {
    const float* x = (const float*)d_in[0];
    const float* w = (const float*)d_in[1];
    float* out = (float*)d_out;

    uhat_kernel<<<NCH1 * 8, 128>>>(x, w);       // u_hat + fused s1 partials
    reduce_stage1<<<1024, 256>>>();
    reduce_stage2<<<128, 256>>>();              // g_V = v1

    routing_kernel<<<dim3(NCHUNK, BB), 256>>>();  // pass 2
    squash_kernel<<<128, 256>>>(out, 1);          // g_V += v2

    routing_kernel<<<dim3(NCHUNK, BB), 256>>>();  // pass 3
    squash_kernel<<<128, 256>>>(out, 2);          // out = v3
}